// round 4
// baseline (speedup 1.0000x reference)
#include <cuda_runtime.h>
#include <cstdint>

// PolicyEncoder gather-sum:
// out[n, :] = bias + w_state0[obs0[n]] + w_state1[obs1[n]] + w_act0[act0[n]] + w_act1[act1[n]]
// N = 262144 rows, D = 128 floats per row.
//
// R4: 256-bit loads (32B/lane). Each half-warp covers one 512B row; one warp
// handles 2 rows. Table gathers use ld.global.nc.L2::evict_last.v8.b32 (the
// only legal evict_last form on sm_103a) so the 77MB of state tables stay
// persist-priority in the 126MB L2 across graph replays, while the 134MB
// output stream is written with st.global.cs (evict-first).

__device__ __forceinline__ void ldg256_evict_last(const float* p, float v[8]) {
    uint32_t r0, r1, r2, r3, r4, r5, r6, r7;
    asm volatile(
        "ld.global.nc.L2::evict_last.v8.b32 {%0,%1,%2,%3,%4,%5,%6,%7}, [%8];"
        : "=r"(r0), "=r"(r1), "=r"(r2), "=r"(r3),
          "=r"(r4), "=r"(r5), "=r"(r6), "=r"(r7)
        : "l"(p));
    v[0] = __uint_as_float(r0); v[1] = __uint_as_float(r1);
    v[2] = __uint_as_float(r2); v[3] = __uint_as_float(r3);
    v[4] = __uint_as_float(r4); v[5] = __uint_as_float(r5);
    v[6] = __uint_as_float(r6); v[7] = __uint_as_float(r7);
}

__global__ void __launch_bounds__(256)
policy_encoder_kernel(const int* __restrict__ obs0,
                      const int* __restrict__ obs1,
                      const int* __restrict__ act0,
                      const int* __restrict__ act1,
                      const float* __restrict__ w0,   // [OBS0, 128] (51MB)
                      const float* __restrict__ w1,   // [OBS1, 128] (26MB)
                      const float* __restrict__ w2,   // [ACT0, 128] (512KB)
                      const float* __restrict__ w3,   // [ACT1, 128] (512KB)
                      const float* __restrict__ bias, // [128]
                      float4* __restrict__ out,       // [N, 32] as float4
                      int n)
{
    const int gtid = blockIdx.x * blockDim.x + threadIdx.x;
    const int warp = gtid >> 5;
    const int lane = gtid & 31;
    const int sub  = lane >> 4;        // 0: first row, 1: second row
    const int l    = lane & 15;        // 16 lanes * 32B = 512B = one row

    const int row = warp * 2 + sub;
    if (row >= n) return;

    const size_t col = (size_t)l * 8;  // float offset of this lane's 8 floats

    // Index loads: broadcast within each half-warp.
    const int i0 = __ldg(obs0 + row);
    const int i1 = __ldg(obs1 + row);
    const int i2 = __ldg(act0 + row);
    const int i3 = __ldg(act1 + row);

    // Issue all 4 gathers back-to-back (MLP=4 x 32B per thread).
    float t0[8], t1[8], t2[8], t3[8];
    ldg256_evict_last(w0 + (size_t)i0 * 128 + col, t0);
    ldg256_evict_last(w1 + (size_t)i1 * 128 + col, t1);
    ldg256_evict_last(w2 + (size_t)i2 * 128 + col, t2);
    ldg256_evict_last(w3 + (size_t)i3 * 128 + col, t3);

    const float4 b0 = __ldg((const float4*)(bias + col));
    const float4 b1 = __ldg((const float4*)(bias + col + 4));

    float4 r0, r1;
    r0.x = b0.x + t0[0] + t1[0] + t2[0] + t3[0];
    r0.y = b0.y + t0[1] + t1[1] + t2[1] + t3[1];
    r0.z = b0.z + t0[2] + t1[2] + t2[2] + t3[2];
    r0.w = b0.w + t0[3] + t1[3] + t2[3] + t3[3];
    r1.x = b1.x + t0[4] + t1[4] + t2[4] + t3[4];
    r1.y = b1.y + t0[5] + t1[5] + t2[5] + t3[5];
    r1.z = b1.z + t0[6] + t1[6] + t2[6] + t3[6];
    r1.w = b1.w + t0[7] + t1[7] + t2[7] + t3[7];

    float4* dst = out + (size_t)row * 32 + l * 2;
    __stcs(dst,     r0);   // evict-first streaming stores
    __stcs(dst + 1, r1);
}

extern "C" void kernel_launch(void* const* d_in, const int* in_sizes, int n_in,
                              void* d_out, int out_size)
{
    const int*   obs0 = (const int*)d_in[0];
    const int*   obs1 = (const int*)d_in[1];
    const int*   act0 = (const int*)d_in[2];
    const int*   act1 = (const int*)d_in[3];
    const float* w0   = (const float*)d_in[4];
    const float* w1   = (const float*)d_in[5];
    const float* w2   = (const float*)d_in[6];
    const float* w3   = (const float*)d_in[7];
    const float* bias = (const float*)d_in[8];
    float4*      out  = (float4*)d_out;

    const int n = in_sizes[0];                 // number of rows (N)
    const int threads = 256;                   // 8 warps/block, 2 rows/warp
    const int rows_per_block = (threads / 32) * 2;   // 16
    const int blocks = (n + rows_per_block - 1) / rows_per_block;

    policy_encoder_kernel<<<blocks, threads>>>(obs0, obs1, act0, act1,
                                               w0, w1, w2, w3, bias, out, n);
}

// round 5
// speedup vs baseline: 1.1291x; 1.1291x over previous
#include <cuda_runtime.h>
#include <cstdint>

// PolicyEncoder gather-sum:
// out[n, :] = bias + w_state0[obs0[n]] + w_state1[obs1[n]] + w_act0[act0[n]] + w_act1[act1[n]]
// N = 262144 rows, D = 128 floats per row.
//
// R5: persistent warps + 2-stage software pipeline.
//  - One exact wave: grid = 148 SMs * 4 blocks, 8 warps/block -> 4736 warps,
//    each grid-strides over ~55 rows. No wave transitions, no warp startup
//    latency per row.
//  - Pipeline: each iteration issues indices for row k+2 and gathers for row
//    k+1, then consumes the (already arrived) gathers of row k. Every warp
//    keeps 4 gathers + 4 index loads in flight at all times.
//  - Output stores stay streaming (__stcs); gathers via __ldg.

struct Idx { int i0, i1, i2, i3; };

__device__ __forceinline__ Idx load_idx(const int* __restrict__ o0,
                                        const int* __restrict__ o1,
                                        const int* __restrict__ a0,
                                        const int* __restrict__ a1, int r) {
    Idx x;
    x.i0 = __ldg(o0 + r);
    x.i1 = __ldg(o1 + r);
    x.i2 = __ldg(a0 + r);
    x.i3 = __ldg(a1 + r);
    return x;
}

__global__ void __launch_bounds__(256, 4)
policy_encoder_kernel(const int* __restrict__ obs0,
                      const int* __restrict__ obs1,
                      const int* __restrict__ act0,
                      const int* __restrict__ act1,
                      const float4* __restrict__ w0,   // [OBS0, 32] as float4
                      const float4* __restrict__ w1,
                      const float4* __restrict__ w2,
                      const float4* __restrict__ w3,
                      const float4* __restrict__ bias, // [32]
                      float4* __restrict__ out,        // [N, 32]
                      int n)
{
    const int lane   = threadIdx.x & 31;
    const int gw     = (int)((blockIdx.x * blockDim.x + threadIdx.x) >> 5);
    const int stride = (int)((gridDim.x * blockDim.x) >> 5);

    if (gw >= n) return;

    const float4 b = __ldg(bias + lane);
    const int last = n - 1;

    // ---- prologue ----
    // iter 0 indices + gathers, iter 1 indices
    Idx ic = load_idx(obs0, obs1, act0, act1, gw);
    int r1 = gw + stride;
    Idx in_ = load_idx(obs0, obs1, act0, act1, r1 <= last ? r1 : last);

    float4 g0 = __ldg(w0 + (size_t)ic.i0 * 32 + lane);
    float4 g1 = __ldg(w1 + (size_t)ic.i1 * 32 + lane);
    float4 g2 = __ldg(w2 + (size_t)ic.i2 * 32 + lane);
    float4 g3 = __ldg(w3 + (size_t)ic.i3 * 32 + lane);

    // ---- steady state ----
    for (int r = gw; r <= last; r += stride) {
        // indices for row r + 2*stride (clamped; waste is negligible at tail)
        int rnn = r + 2 * stride;
        Idx inn = load_idx(obs0, obs1, act0, act1, rnn <= last ? rnn : last);

        // gathers for row r + stride (indices arrived last iteration)
        float4 h0 = __ldg(w0 + (size_t)in_.i0 * 32 + lane);
        float4 h1 = __ldg(w1 + (size_t)in_.i1 * 32 + lane);
        float4 h2 = __ldg(w2 + (size_t)in_.i2 * 32 + lane);
        float4 h3 = __ldg(w3 + (size_t)in_.i3 * 32 + lane);

        // consume row r (gathers issued one iteration ago)
        float4 res;
        res.x = b.x + g0.x + g1.x + g2.x + g3.x;
        res.y = b.y + g0.y + g1.y + g2.y + g3.y;
        res.z = b.z + g0.z + g1.z + g2.z + g3.z;
        res.w = b.w + g0.w + g1.w + g2.w + g3.w;
        __stcs(out + (size_t)r * 32 + lane, res);

        // rotate pipeline registers
        g0 = h0; g1 = h1; g2 = h2; g3 = h3;
        in_ = inn;
    }
}

extern "C" void kernel_launch(void* const* d_in, const int* in_sizes, int n_in,
                              void* d_out, int out_size)
{
    const int*    obs0 = (const int*)d_in[0];
    const int*    obs1 = (const int*)d_in[1];
    const int*    act0 = (const int*)d_in[2];
    const int*    act1 = (const int*)d_in[3];
    const float4* w0   = (const float4*)d_in[4];
    const float4* w1   = (const float4*)d_in[5];
    const float4* w2   = (const float4*)d_in[6];
    const float4* w3   = (const float4*)d_in[7];
    const float4* bias = (const float4*)d_in[8];
    float4*       out  = (float4*)d_out;

    const int n = in_sizes[0];     // number of rows (N)
    const int threads = 256;       // 8 warps/block
    const int blocks  = 148 * 4;   // one exact wave at 4 blocks/SM

    policy_encoder_kernel<<<blocks, threads>>>(obs0, obs1, act0, act1,
                                               w0, w1, w2, w3, bias, out, n);
}